// round 2
// baseline (speedup 1.0000x reference)
#include <cuda_runtime.h>
#include <cuda_bf16.h>
#include <math.h>

#define BT   2048
#define TPH  32
#define EDIM 128
#define HDIM 256
#define GDIM 1024
#define VOC  256

// ---------------- device scratch (no allocation allowed) ----------------
__device__ float g_encProj[VOC * GDIM];   // emb @ enc_Wih^T + biases
__device__ float g_decProj[VOC * GDIM];   // emb @ dec_Wih^T + biases
__device__ float g_hA[BT * HDIM];
__device__ float g_hB[BT * HDIM];
__device__ float g_c[BT * HDIM];
__device__ float g_encLast[BT * HDIM];
__device__ int   g_tok[BT];

// ---------------- proj table: tab[v][n] = dot(emb[v], W[n]) + b1[n] + b2[n] ----
__global__ void proj_kernel(const float* __restrict__ emb,
                            const float* __restrict__ W,
                            const float* __restrict__ b1,
                            const float* __restrict__ b2,
                            int which)
{
    float* tab = which ? g_decProj : g_encProj;
    int v = blockIdx.x;
    __shared__ float es[EDIM];
    int tid = threadIdx.x;
    if (tid < EDIM) es[tid] = emb[v * EDIM + tid];
    __syncthreads();

    for (int n = tid; n < GDIM; n += blockDim.x) {
        const float4* wr = (const float4*)(W + (size_t)n * EDIM);
        float acc = 0.f;
#pragma unroll
        for (int k4 = 0; k4 < EDIM / 4; k4++) {
            float4 w = wr[k4];
            acc += es[k4 * 4 + 0] * w.x + es[k4 * 4 + 1] * w.y
                 + es[k4 * 4 + 2] * w.z + es[k4 * 4 + 3] * w.w;
        }
        tab[(size_t)v * GDIM + n] = acc + b1[n] + b2[n];
    }
}

// ---------------- init: h=0, c=0 ----------------
__global__ void init_kernel()
{
    int i = blockIdx.x * blockDim.x + threadIdx.x;
    if (i < BT * HDIM) { g_hA[i] = 0.f; g_c[i] = 0.f; }
}

// ---------------- decoder init: h=encLast, c=0, tok=sos ----------------
__global__ void dec_init_kernel(const int* __restrict__ sos)
{
    int i = blockIdx.x * blockDim.x + threadIdx.x;
    if (i < BT * HDIM) { g_hA[i] = g_encLast[i]; g_c[i] = 0.f; }
    if (i < BT) g_tok[i] = sos[0];
}

// ---------------- fused LSTM step: gates = proj[tok] + h @ Whh^T, pointwise ---
// Block tile: 64 rows (m) x 32 hidden units (j), computing all 4 gates per j.
// Thread (256/blk): tm=tid>>5 owns 8 m rows, tn=tid&31 owns 1 j (4 gates).
__global__ void __launch_bounds__(256)
lstm_step_kernel(const float* __restrict__ Whh,
                 const int*   __restrict__ ext_tokens, // phonemes (enc) or null
                 const int*   __restrict__ lens,       // enc only
                 int mode,                              // 0=enc, 1=dec
                 int t)
{
    const float* hin  = (t & 1) ? g_hB : g_hA;
    float*       hout = (t & 1) ? g_hA : g_hB;
    const float* proj = mode ? g_decProj : g_encProj;

    __shared__ float As[16][68];    // [kk][mm] h tile (transposed)
    __shared__ float Bs[16][132];   // [kk][nn] Whh tile; nn -> (j=nn/4, gate=nn%4)

    const int tid = threadIdx.x;
    const int tn = tid & 31;
    const int tm = tid >> 5;
    const int m0 = blockIdx.x * 64;
    const int j0 = blockIdx.y * 32;

    float acc[8][4];
#pragma unroll
    for (int i = 0; i < 8; i++)
#pragma unroll
        for (int j = 0; j < 4; j++) acc[i][j] = 0.f;

    for (int k0 = 0; k0 < HDIM; k0 += 16) {
        // load h tile 64x16
        {
            int r = tid >> 2, kq = tid & 3;
            float4 v = *(const float4*)(hin + (size_t)(m0 + r) * HDIM + k0 + kq * 4);
            As[kq * 4 + 0][r] = v.x; As[kq * 4 + 1][r] = v.y;
            As[kq * 4 + 2][r] = v.z; As[kq * 4 + 3][r] = v.w;
        }
        // load Whh tile 128x16 (rows = gate*256 + j)
#pragma unroll
        for (int i = 0; i < 2; i++) {
            int f = tid + i * 256;
            int nn = f >> 2, kq = f & 3;
            int grow = (nn & 3) * HDIM + j0 + (nn >> 2);
            float4 v = *(const float4*)(Whh + (size_t)grow * HDIM + k0 + kq * 4);
            Bs[kq * 4 + 0][nn] = v.x; Bs[kq * 4 + 1][nn] = v.y;
            Bs[kq * 4 + 2][nn] = v.z; Bs[kq * 4 + 3][nn] = v.w;
        }
        __syncthreads();
#pragma unroll
        for (int kk = 0; kk < 16; kk++) {
            float4 b  = *(const float4*)&Bs[kk][tn * 4];
            float4 a0 = *(const float4*)&As[kk][tm * 8];
            float4 a1 = *(const float4*)&As[kk][tm * 8 + 4];
            float av[8] = {a0.x, a0.y, a0.z, a0.w, a1.x, a1.y, a1.z, a1.w};
            float bv[4] = {b.x, b.y, b.z, b.w};
#pragma unroll
            for (int mi = 0; mi < 8; mi++)
#pragma unroll
                for (int gi = 0; gi < 4; gi++)
                    acc[mi][gi] += av[mi] * bv[gi];
        }
        __syncthreads();
    }

    const int j = j0 + tn;
#pragma unroll
    for (int mi = 0; mi < 8; mi++) {
        const int m = m0 + tm * 8 + mi;
        const int tk = mode ? g_tok[m] : ext_tokens[m * TPH + t];
        const float* pr = proj + (size_t)tk * GDIM;
        float xi = acc[mi][0] + pr[j];
        float xf = acc[mi][1] + pr[HDIM + j];
        float xg = acc[mi][2] + pr[2 * HDIM + j];
        float xo = acc[mi][3] + pr[3 * HDIM + j];
        float iv = 1.f / (1.f + expf(-xi));
        float fv = 1.f / (1.f + expf(-xf));
        float gv = tanhf(xg);
        float ov = 1.f / (1.f + expf(-xo));
        size_t idx = (size_t)m * HDIM + j;
        float cn = fv * g_c[idx] + iv * gv;
        g_c[idx] = cn;
        float hv = ov * tanhf(cn);
        hout[idx] = hv;
        if (!mode && t == lens[m] - 1) g_encLast[idx] = hv;
    }
}

// ---------------- decoder fc + argmax: scores = h @ fcW^T + fcb --------------
// Block: 32 rows x full V=256. Thread: tm=tid>>5 owns 4 m, tv=tid&31 owns 8 v.
// A warp shares tm -> per-row argmax is a warp shuffle reduction.
__global__ void __launch_bounds__(256)
dec_fc_kernel(const float* __restrict__ fcW,
              const float* __restrict__ fcb,
              float* __restrict__ out,
              int t)
{
    const float* h = (t & 1) ? g_hA : g_hB;   // h written by step t

    __shared__ float As[16][36];
    __shared__ float Bs[16][264];

    const int tid = threadIdx.x;
    const int tv = tid & 31;
    const int tm = tid >> 5;
    const int m0 = blockIdx.x * 32;

    float acc[4][8];
#pragma unroll
    for (int i = 0; i < 4; i++)
#pragma unroll
        for (int j = 0; j < 8; j++) acc[i][j] = 0.f;

    for (int k0 = 0; k0 < HDIM; k0 += 16) {
        if (tid < 128) {
            int r = tid >> 2, kq = tid & 3;
            float4 v = *(const float4*)(h + (size_t)(m0 + r) * HDIM + k0 + kq * 4);
            As[kq * 4 + 0][r] = v.x; As[kq * 4 + 1][r] = v.y;
            As[kq * 4 + 2][r] = v.z; As[kq * 4 + 3][r] = v.w;
        }
#pragma unroll
        for (int i = 0; i < 4; i++) {
            int f = tid + i * 256;
            int row = f >> 2, kq = f & 3;
            float4 v = *(const float4*)(fcW + (size_t)row * HDIM + k0 + kq * 4);
            Bs[kq * 4 + 0][row] = v.x; Bs[kq * 4 + 1][row] = v.y;
            Bs[kq * 4 + 2][row] = v.z; Bs[kq * 4 + 3][row] = v.w;
        }
        __syncthreads();
#pragma unroll
        for (int kk = 0; kk < 16; kk++) {
            float4 a  = *(const float4*)&As[kk][tm * 4];
            float4 b0 = *(const float4*)&Bs[kk][tv * 8];
            float4 b1 = *(const float4*)&Bs[kk][tv * 8 + 4];
            float av[4] = {a.x, a.y, a.z, a.w};
            float bv[8] = {b0.x, b0.y, b0.z, b0.w, b1.x, b1.y, b1.z, b1.w};
#pragma unroll
            for (int mi = 0; mi < 4; mi++)
#pragma unroll
                for (int vi = 0; vi < 8; vi++)
                    acc[mi][vi] += av[mi] * bv[vi];
        }
        __syncthreads();
    }

    float bias[8];
#pragma unroll
    for (int vi = 0; vi < 8; vi++) bias[vi] = fcb[tv * 8 + vi];

#pragma unroll
    for (int mi = 0; mi < 4; mi++) {
        const int m = m0 + tm * 4 + mi;
        float s[8];
#pragma unroll
        for (int vi = 0; vi < 8; vi++) s[vi] = acc[mi][vi] + bias[vi];

        // write scores
        float* orow = out + (size_t)m * (TPH * VOC) + (size_t)t * VOC + tv * 8;
        float4 w0 = make_float4(s[0], s[1], s[2], s[3]);
        float4 w1 = make_float4(s[4], s[5], s[6], s[7]);
        *(float4*)(orow)     = w0;
        *(float4*)(orow + 4) = w1;

        // argmax (first-max-wins tie-break, matching jnp.argmax)
        float bv = s[0];
        int   bi = tv * 8;
#pragma unroll
        for (int vi = 1; vi < 8; vi++) {
            if (s[vi] > bv) { bv = s[vi]; bi = tv * 8 + vi; }
        }
#pragma unroll
        for (int off = 16; off > 0; off >>= 1) {
            float ov = __shfl_xor_sync(0xffffffffu, bv, off);
            int   oi = __shfl_xor_sync(0xffffffffu, bi, off);
            if (ov > bv || (ov == bv && oi < bi)) { bv = ov; bi = oi; }
        }
        if (tv == 0) g_tok[m] = bi;
    }
}

// ---------------- launch ----------------
extern "C" void kernel_launch(void* const* d_in, const int* in_sizes, int n_in,
                              void* d_out, int out_size)
{
    const int*   phon    = (const int*)  d_in[0];   // (B,T,TP) int32
    const int*   plen    = (const int*)  d_in[1];   // (B,T) int32
    const float* emb     = (const float*)d_in[2];
    const float* encWih  = (const float*)d_in[3];
    const float* encWhh  = (const float*)d_in[4];
    const float* encBih  = (const float*)d_in[5];
    const float* encBhh  = (const float*)d_in[6];
    const float* decWih  = (const float*)d_in[7];
    const float* decWhh  = (const float*)d_in[8];
    const float* decBih  = (const float*)d_in[9];
    const float* decBhh  = (const float*)d_in[10];
    const float* fcW     = (const float*)d_in[11];
    const float* fcb     = (const float*)d_in[12];
    const int*   sos     = (const int*)  d_in[13];
    float* out = (float*)d_out;

    // fold input projections + both biases into per-token tables
    proj_kernel<<<VOC, 256>>>(emb, encWih, encBih, encBhh, 0);
    proj_kernel<<<VOC, 256>>>(emb, decWih, decBih, decBhh, 1);

    init_kernel<<<(BT * HDIM + 255) / 256, 256>>>();

    // encoder: 32 recurrent steps (double-buffered h)
    for (int t = 0; t < TPH; t++)
        lstm_step_kernel<<<dim3(BT / 64, HDIM / 32), 256>>>(encWhh, phon, plen, 0, t);

    dec_init_kernel<<<(BT * HDIM + 255) / 256, 256>>>(sos);

    // decoder: 32 steps of (LSTM step, fc + argmax feedback)
    for (int t = 0; t < TPH; t++) {
        lstm_step_kernel<<<dim3(BT / 64, HDIM / 32), 256>>>(decWhh, nullptr, nullptr, 1, t);
        dec_fc_kernel<<<BT / 32, 256>>>(fcW, fcb, out, t);
    }
}

// round 4
// speedup vs baseline: 1.1210x; 1.1210x over previous
#include <cuda_runtime.h>
#include <cuda_fp16.h>
#include <math.h>
#include <stdint.h>

#define BT   2048
#define TPH  32
#define EDIM 128
#define HDIM 256
#define GDIM 1024
#define VOC  256

#define MT 128
#define NT 128
#define GRID_M (BT / MT)     // 16
#define GRID_N (GDIM / NT)   // 8

// smem: A/B stages (double buffered) then C staging
// A stage: 128 rows x 40 halfs (pad 32->40) = 10240 B ; B same
#define STG_BYTES   10240
#define SM_C_OFF    40960
#define C_STRIDE    132
#define SM_TOTAL    (40960 + 128 * C_STRIDE * 4)   // 108544

// ---------------- device scratch ----------------
__device__ float   g_projP[2][VOC * GDIM];   // permuted proj tables (enc/dec)
__device__ __half  g_Ws[2][2][GDIM * HDIM];  // Whh fp16 splits (hi,lo), gate-interleaved rows
__device__ __half  g_hs[2][2][BT * HDIM];    // h fp16 splits, double buffered by parity
__device__ __half  g_eL[2][BT * HDIM];       // encoder-last h splits
__device__ float   g_c[BT * HDIM];
__device__ float   g_hf[BT * HDIM];          // fp32 h (decoder, for fc)
__device__ int     g_tok[BT];

// ---------------- PTX helpers (portable: sm_80+) ----------------
__device__ __forceinline__ uint32_t smem_u32(const void* p) {
    uint32_t a;
    asm("{ .reg .u64 t; cvta.to.shared.u64 t, %1; cvt.u32.u64 %0, t; }" : "=r"(a) : "l"(p));
    return a;
}
__device__ __forceinline__ void cpa16(uint32_t saddr, const void* g) {
    asm volatile("cp.async.cg.shared.global [%0], [%1], 16;" :: "r"(saddr), "l"(g));
}
__device__ __forceinline__ void cpa_commit() {
    asm volatile("cp.async.commit_group;" ::: "memory");
}
template <int N>
__device__ __forceinline__ void cpa_wait() {
    asm volatile("cp.async.wait_group %0;" :: "n"(N) : "memory");
}
__device__ __forceinline__ void ldsm4(uint32_t* r, uint32_t addr) {
    asm volatile("ldmatrix.sync.aligned.m8n8.x4.shared.b16 {%0,%1,%2,%3}, [%4];"
        : "=r"(r[0]), "=r"(r[1]), "=r"(r[2]), "=r"(r[3]) : "r"(addr));
}
__device__ __forceinline__ void mma16816(float* c, const uint32_t* a,
                                         uint32_t b0, uint32_t b1) {
    asm volatile("mma.sync.aligned.m16n8k16.row.col.f32.f16.f16.f32 "
        "{%0,%1,%2,%3}, {%4,%5,%6,%7}, {%8,%9}, {%0,%1,%2,%3};"
        : "+f"(c[0]), "+f"(c[1]), "+f"(c[2]), "+f"(c[3])
        : "r"(a[0]), "r"(a[1]), "r"(a[2]), "r"(a[3]), "r"(b0), "r"(b1));
}

// ---------------- prep: split Whh into 2 fp16 planes, gate-interleaved rows --
__global__ void split_w_kernel(const float* __restrict__ W, int which)
{
    int idx = blockIdx.x * blockDim.x + threadIdx.x;   // over GDIM*HDIM
    if (idx >= GDIM * HDIM) return;
    int np = idx >> 8, k = idx & 255;
    int j = np >> 2, g = np & 3;                        // n' = j*4 + g
    float w = W[(size_t)(g * HDIM + j) * HDIM + k];
    __half hi = __float2half_rn(w);
    __half lo = __float2half_rn(w - __half2float(hi));
    g_Ws[which][0][idx] = hi;
    g_Ws[which][1][idx] = lo;
}

// ---------------- prep: permuted proj table -----------------------------
__global__ void proj_kernel(const float* __restrict__ emb,
                            const float* __restrict__ W,
                            const float* __restrict__ b1,
                            const float* __restrict__ b2,
                            int which)
{
    int v = blockIdx.x;
    __shared__ float es[EDIM];
    int tid = threadIdx.x;
    if (tid < EDIM) es[tid] = emb[v * EDIM + tid];
    __syncthreads();
    for (int n = tid; n < GDIM; n += blockDim.x) {
        const float4* wr = (const float4*)(W + (size_t)n * EDIM);
        float acc = 0.f;
#pragma unroll
        for (int k4 = 0; k4 < EDIM / 4; k4++) {
            float4 w = wr[k4];
            acc += es[k4 * 4 + 0] * w.x + es[k4 * 4 + 1] * w.y
                 + es[k4 * 4 + 2] * w.z + es[k4 * 4 + 3] * w.w;
        }
        int np = (n & 255) * 4 + (n >> 8);
        g_projP[which][(size_t)v * GDIM + np] = acc + b1[n] + b2[n];
    }
}

// ---------------- init / dec-init ----------------
__global__ void init_kernel()
{
    int i = blockIdx.x * blockDim.x + threadIdx.x;
    if (i < BT * HDIM) {
        __half z = __float2half_rn(0.f);
        g_hs[0][0][i] = z; g_hs[0][1][i] = z;
        g_c[i] = 0.f;
    }
}
__global__ void dec_init_kernel(const int* __restrict__ sos)
{
    int i = blockIdx.x * blockDim.x + threadIdx.x;
    if (i < BT * HDIM) {
        g_hs[0][0][i] = g_eL[0][i];
        g_hs[0][1][i] = g_eL[1][i];
        g_c[i] = 0.f;
    }
    if (i < BT) g_tok[i] = sos[0];
}

// ---------------- fused LSTM step: fp16-split mma.sync GEMM + pointwise -----
// C[2048,1024'] = Ah.Bh + Ah.Bl + Al.Bh  (K' = 3*256 = 768, fp32 accum)
// CTA tile 128x128, 8 warps (2M x 4N), warp tile 64x32, k-stage 32.
__global__ __launch_bounds__(256, 1)
void lstm_step_mma(const int* __restrict__ phon, const int* __restrict__ lens,
                   int mode, int t)
{
    extern __shared__ char smem[];
    const uint32_t sb = smem_u32(smem);
    float* Cst = (float*)(smem + SM_C_OFF);

    const int tid  = threadIdx.x;
    const int wid  = tid >> 5;
    const int lane = tid & 31;
    const int wm = wid & 1, wn = wid >> 1;
    const int m0 = blockIdx.x * MT;
    const int n0 = blockIdx.y * NT;
    const int j0 = n0 >> 2;
    const int inPar = t & 1, outPar = inPar ^ 1;

    const __half* Asrc[3] = { g_hs[inPar][0], g_hs[inPar][0], g_hs[inPar][1] };
    const __half* Bsrc[3] = { g_Ws[mode][0],  g_Ws[mode][1],  g_Ws[mode][0]  };

    float acc[4][4][4];
#pragma unroll
    for (int i = 0; i < 4; i++)
#pragma unroll
        for (int j = 0; j < 4; j++)
#pragma unroll
            for (int q = 0; q < 4; q++) acc[i][j][q] = 0.f;

    // per-lane ldmatrix base offsets (bytes, row stride = 40 halfs = 80 B)
    const int aRow = wm * 64 + (lane & 15);
    const int aCol = (lane >> 4) * 8;
    const int bRow = wn * 32 + ((lane & 16) >> 1) + (lane & 7);
    const int bCol = ((lane >> 3) & 1) * 8;

    const int ldRow = tid >> 2, ldC4 = tid & 3;     // cp.async mapping

    // ---- prologue: stage 0 ----
    {
        const __half* As = Asrc[0];
        const __half* Bs = Bsrc[0];
        uint32_t sA = sb, sB = sb + STG_BYTES;
#pragma unroll
        for (int i = 0; i < 2; i++) {
            int row = ldRow + i * 64;
            uint32_t so = (uint32_t)(row * 40 + ldC4 * 8) * 2;
            cpa16(sA + so, As + (size_t)(m0 + row) * HDIM + ldC4 * 8);
            cpa16(sB + so, Bs + (size_t)(n0 + row) * HDIM + ldC4 * 8);
        }
        cpa_commit();
    }

    for (int st = 0; st < 24; st++) {
        const int buf = st & 1;
        if (st < 23) {
            const int sn = st + 1;
            const int seg = sn >> 3, kb = (sn & 7) * 32;
            const __half* As = Asrc[seg];
            const __half* Bs = Bsrc[seg];
            uint32_t sA = sb + (buf ^ 1) * 2 * STG_BYTES;
            uint32_t sB = sA + STG_BYTES;
#pragma unroll
            for (int i = 0; i < 2; i++) {
                int row = ldRow + i * 64;
                uint32_t so = (uint32_t)(row * 40 + ldC4 * 8) * 2;
                cpa16(sA + so, As + (size_t)(m0 + row) * HDIM + kb + ldC4 * 8);
                cpa16(sB + so, Bs + (size_t)(n0 + row) * HDIM + kb + ldC4 * 8);
            }
            cpa_commit();
            cpa_wait<1>();
        } else {
            cpa_wait<0>();
        }
        __syncthreads();

        const uint32_t sA = sb + buf * 2 * STG_BYTES;
        const uint32_t sB = sA + STG_BYTES;
#pragma unroll
        for (int k16 = 0; k16 < 2; k16++) {
            uint32_t a[4][4];
#pragma unroll
            for (int mt = 0; mt < 4; mt++)
                ldsm4(a[mt], sA + (uint32_t)((aRow + mt * 16) * 40 + k16 * 16 + aCol) * 2);
            uint32_t b[2][4];
#pragma unroll
            for (int bg = 0; bg < 2; bg++)
                ldsm4(b[bg], sB + (uint32_t)((bRow + bg * 16) * 40 + k16 * 16 + bCol) * 2);
#pragma unroll
            for (int mt = 0; mt < 4; mt++)
#pragma unroll
                for (int nt = 0; nt < 4; nt++)
                    mma16816(acc[mt][nt], a[mt], b[nt >> 1][(nt & 1) * 2],
                             b[nt >> 1][(nt & 1) * 2 + 1]);
        }
        __syncthreads();
    }

    // ---- stage accumulators to smem C (gate-interleaved columns) ----
#pragma unroll
    for (int mt = 0; mt < 4; mt++) {
#pragma unroll
        for (int nt = 0; nt < 4; nt++) {
            int r0 = wm * 64 + mt * 16 + (lane >> 2);
            int c0 = wn * 32 + nt * 8 + (lane & 3) * 2;
            *(float2*)&Cst[r0 * C_STRIDE + c0]       = make_float2(acc[mt][nt][0], acc[mt][nt][1]);
            *(float2*)&Cst[(r0 + 8) * C_STRIDE + c0] = make_float2(acc[mt][nt][2], acc[mt][nt][3]);
        }
    }
    __syncthreads();

    // ---- pointwise LSTM epilogue ----
    const float* projT = g_projP[mode];
#pragma unroll
    for (int i = 0; i < 16; i++) {
        int f = tid + i * 256;
        int lm = f >> 5, jl = f & 31;
        int m = m0 + lm;
        int tok = mode ? g_tok[m] : phon[m * TPH + t];
        float4 gv4 = *(const float4*)&Cst[lm * C_STRIDE + jl * 4];
        float4 pv  = *(const float4*)&projT[(size_t)tok * GDIM + (n0 + jl * 4)];
        float xi = gv4.x + pv.x;
        float xf = gv4.y + pv.y;
        float xg = gv4.z + pv.z;
        float xo = gv4.w + pv.w;
        float iv = 1.f / (1.f + expf(-xi));
        float fv = 1.f / (1.f + expf(-xf));
        float gg = tanhf(xg);
        float ov = 1.f / (1.f + expf(-xo));
        size_t idx = (size_t)m * HDIM + j0 + jl;
        float cn = fv * g_c[idx] + iv * gg;
        g_c[idx] = cn;
        float hv = ov * tanhf(cn);
        __half hi = __float2half_rn(hv);
        __half lo = __float2half_rn(hv - __half2float(hi));
        g_hs[outPar][0][idx] = hi;
        g_hs[outPar][1][idx] = lo;
        if (mode) {
            g_hf[idx] = hv;
        } else if (t == lens[m] - 1) {
            g_eL[0][idx] = hi; g_eL[1][idx] = lo;
        }
    }
}

// ---------------- decoder fc + argmax (unchanged from R2, reads g_hf) -------
__global__ void __launch_bounds__(256)
dec_fc_kernel(const float* __restrict__ fcW,
              const float* __restrict__ fcb,
              float* __restrict__ out,
              int t)
{
    const float* h = g_hf;

    __shared__ float As[16][36];
    __shared__ float Bs[16][264];

    const int tid = threadIdx.x;
    const int tv = tid & 31;
    const int tm = tid >> 5;
    const int m0 = blockIdx.x * 32;

    float acc[4][8];
#pragma unroll
    for (int i = 0; i < 4; i++)
#pragma unroll
        for (int j = 0; j < 8; j++) acc[i][j] = 0.f;

    for (int k0 = 0; k0 < HDIM; k0 += 16) {
        if (tid < 128) {
            int r = tid >> 2, kq = tid & 3;
            float4 v = *(const float4*)(h + (size_t)(m0 + r) * HDIM + k0 + kq * 4);
            As[kq * 4 + 0][r] = v.x; As[kq * 4 + 1][r] = v.y;
            As[kq * 4 + 2][r] = v.z; As[kq * 4 + 3][r] = v.w;
        }
#pragma unroll
        for (int i = 0; i < 4; i++) {
            int f = tid + i * 256;
            int row = f >> 2, kq = f & 3;
            float4 v = *(const float4*)(fcW + (size_t)row * HDIM + k0 + kq * 4);
            Bs[kq * 4 + 0][row] = v.x; Bs[kq * 4 + 1][row] = v.y;
            Bs[kq * 4 + 2][row] = v.z; Bs[kq * 4 + 3][row] = v.w;
        }
        __syncthreads();
#pragma unroll
        for (int kk = 0; kk < 16; kk++) {
            float4 a  = *(const float4*)&As[kk][tm * 4];
            float4 b0 = *(const float4*)&Bs[kk][tv * 8];
            float4 b1 = *(const float4*)&Bs[kk][tv * 8 + 4];
            float av[4] = {a.x, a.y, a.z, a.w};
            float bv[8] = {b0.x, b0.y, b0.z, b0.w, b1.x, b1.y, b1.z, b1.w};
#pragma unroll
            for (int mi = 0; mi < 4; mi++)
#pragma unroll
                for (int vi = 0; vi < 8; vi++)
                    acc[mi][vi] += av[mi] * bv[vi];
        }
        __syncthreads();
    }

    float bias[8];
#pragma unroll
    for (int vi = 0; vi < 8; vi++) bias[vi] = fcb[tv * 8 + vi];

#pragma unroll
    for (int mi = 0; mi < 4; mi++) {
        const int m = m0 + tm * 4 + mi;
        float s[8];
#pragma unroll
        for (int vi = 0; vi < 8; vi++) s[vi] = acc[mi][vi] + bias[vi];

        float* orow = out + (size_t)m * (TPH * VOC) + (size_t)t * VOC + tv * 8;
        *(float4*)(orow)     = make_float4(s[0], s[1], s[2], s[3]);
        *(float4*)(orow + 4) = make_float4(s[4], s[5], s[6], s[7]);

        float bv = s[0];
        int   bi = tv * 8;
#pragma unroll
        for (int vi = 1; vi < 8; vi++)
            if (s[vi] > bv) { bv = s[vi]; bi = tv * 8 + vi; }
#pragma unroll
        for (int off = 16; off > 0; off >>= 1) {
            float ov = __shfl_xor_sync(0xffffffffu, bv, off);
            int   oi = __shfl_xor_sync(0xffffffffu, bi, off);
            if (ov > bv || (ov == bv && oi < bi)) { bv = ov; bi = oi; }
        }
        if (tv == 0) g_tok[m] = bi;
    }
}

// ---------------- launch ----------------
extern "C" void kernel_launch(void* const* d_in, const int* in_sizes, int n_in,
                              void* d_out, int out_size)
{
    const int*   phon   = (const int*)  d_in[0];
    const int*   plen   = (const int*)  d_in[1];
    const float* emb    = (const float*)d_in[2];
    const float* encWih = (const float*)d_in[3];
    const float* encWhh = (const float*)d_in[4];
    const float* encBih = (const float*)d_in[5];
    const float* encBhh = (const float*)d_in[6];
    const float* decWih = (const float*)d_in[7];
    const float* decWhh = (const float*)d_in[8];
    const float* decBih = (const float*)d_in[9];
    const float* decBhh = (const float*)d_in[10];
    const float* fcW    = (const float*)d_in[11];
    const float* fcb    = (const float*)d_in[12];
    const int*   sos    = (const int*)  d_in[13];
    float* out = (float*)d_out;

    cudaFuncSetAttribute(lstm_step_mma,
                         cudaFuncAttributeMaxDynamicSharedMemorySize, SM_TOTAL);

    split_w_kernel<<<(GDIM * HDIM + 255) / 256, 256>>>(encWhh, 0);
    split_w_kernel<<<(GDIM * HDIM + 255) / 256, 256>>>(decWhh, 1);
    proj_kernel<<<VOC, 256>>>(emb, encWih, encBih, encBhh, 0);
    proj_kernel<<<VOC, 256>>>(emb, decWih, decBih, decBhh, 1);

    init_kernel<<<(BT * HDIM + 255) / 256, 256>>>();

    dim3 grid(GRID_M, GRID_N);
    for (int t = 0; t < TPH; t++)
        lstm_step_mma<<<grid, 256, SM_TOTAL>>>(phon, plen, 0, t);

    dec_init_kernel<<<(BT * HDIM + 255) / 256, 256>>>(sos);

    for (int t = 0; t < TPH; t++) {
        lstm_step_mma<<<grid, 256, SM_TOTAL>>>(phon, plen, 1, t);
        dec_fc_kernel<<<BT / 32, 256>>>(fcW, fcb, out, t);
    }
}

// round 5
// speedup vs baseline: 1.2000x; 1.0705x over previous
#include <cuda_runtime.h>
#include <cuda_fp16.h>
#include <math.h>
#include <stdint.h>

#define BT   2048
#define TPH  32
#define EDIM 128
#define HDIM 256
#define GDIM 1024
#define VOC  256

#define MT 128
#define NT 128
#define GRID_M (BT / MT)     // 16
#define GRID_N (GDIM / NT)   // 8

// tiles: 128 rows x 64 k halfs, padded row stride 72 halfs (144 B)
#define TROW_B   144
#define TILE_B   (128 * TROW_B)          // 18432
#define BUF_B    (4 * TILE_B)            // Ah, Al, Bh, Bl = 73728
#define SM_C_OFF (2 * BUF_B)             // 147456
#define C_STRIDE 132
#define SM_TOTAL (SM_C_OFF + 128 * C_STRIDE * 4)   // 215040

// ---------------- device scratch ----------------
__device__ float   g_projP[2][VOC * GDIM];   // permuted proj tables (enc/dec)
__device__ __half  g_Ws[2][2][GDIM * HDIM];  // Whh fp16 splits (hi,lo), gate-interleaved rows
__device__ __half  g_hs[2][2][BT * HDIM];    // h fp16 splits, double buffered by parity
__device__ __half  g_eL[2][BT * HDIM];       // encoder-last h splits
__device__ float   g_c[BT * HDIM];
__device__ float   g_hf[BT * HDIM];          // fp32 h (decoder, for fc)
__device__ int     g_tok[BT];

// ---------------- PTX helpers (portable: sm_80+) ----------------
__device__ __forceinline__ uint32_t smem_u32(const void* p) {
    uint32_t a;
    asm("{ .reg .u64 t; cvta.to.shared.u64 t, %1; cvt.u32.u64 %0, t; }" : "=r"(a) : "l"(p));
    return a;
}
__device__ __forceinline__ void cpa16(uint32_t saddr, const void* g) {
    asm volatile("cp.async.cg.shared.global [%0], [%1], 16;" :: "r"(saddr), "l"(g));
}
__device__ __forceinline__ void cpa_commit() {
    asm volatile("cp.async.commit_group;" ::: "memory");
}
template <int N>
__device__ __forceinline__ void cpa_wait() {
    asm volatile("cp.async.wait_group %0;" :: "n"(N) : "memory");
}
__device__ __forceinline__ void ldsm4(uint32_t* r, uint32_t addr) {
    asm volatile("ldmatrix.sync.aligned.m8n8.x4.shared.b16 {%0,%1,%2,%3}, [%4];"
        : "=r"(r[0]), "=r"(r[1]), "=r"(r[2]), "=r"(r[3]) : "r"(addr));
}
__device__ __forceinline__ void mma16816(float* c, const uint32_t* a,
                                         uint32_t b0, uint32_t b1) {
    asm volatile("mma.sync.aligned.m16n8k16.row.col.f32.f16.f16.f32 "
        "{%0,%1,%2,%3}, {%4,%5,%6,%7}, {%8,%9}, {%0,%1,%2,%3};"
        : "+f"(c[0]), "+f"(c[1]), "+f"(c[2]), "+f"(c[3])
        : "r"(a[0]), "r"(a[1]), "r"(a[2]), "r"(a[3]), "r"(b0), "r"(b1));
}

// ---------------- prep: split Whh into 2 fp16 planes, gate-interleaved rows --
__global__ void split_w_kernel(const float* __restrict__ W, int which)
{
    int idx = blockIdx.x * blockDim.x + threadIdx.x;   // over GDIM*HDIM
    if (idx >= GDIM * HDIM) return;
    int np = idx >> 8, k = idx & 255;
    int j = np >> 2, g = np & 3;                        // n' = j*4 + g
    float w = W[(size_t)(g * HDIM + j) * HDIM + k];
    __half hi = __float2half_rn(w);
    __half lo = __float2half_rn(w - __half2float(hi));
    g_Ws[which][0][idx] = hi;
    g_Ws[which][1][idx] = lo;
}

// ---------------- prep: permuted proj table (1024 blocks, 1 n per thread) ----
__global__ void proj_kernel(const float* __restrict__ emb,
                            const float* __restrict__ W,
                            const float* __restrict__ b1,
                            const float* __restrict__ b2,
                            int which)
{
    int v = blockIdx.x;
    __shared__ float es[EDIM];
    int tid = threadIdx.x;
    if (tid < EDIM) es[tid] = emb[v * EDIM + tid];
    __syncthreads();
    int n = blockIdx.y * 256 + tid;
    const float4* wr = (const float4*)(W + (size_t)n * EDIM);
    float acc = 0.f;
#pragma unroll
    for (int k4 = 0; k4 < EDIM / 4; k4++) {
        float4 w = wr[k4];
        acc += es[k4 * 4 + 0] * w.x + es[k4 * 4 + 1] * w.y
             + es[k4 * 4 + 2] * w.z + es[k4 * 4 + 3] * w.w;
    }
    int np = (n & 255) * 4 + (n >> 8);
    g_projP[which][(size_t)v * GDIM + np] = acc + b1[n] + b2[n];
}

// ---------------- init / dec-init ----------------
__global__ void init_kernel()
{
    int i = blockIdx.x * blockDim.x + threadIdx.x;
    if (i < BT * HDIM) {
        __half z = __float2half_rn(0.f);
        g_hs[0][0][i] = z; g_hs[0][1][i] = z;
        g_c[i] = 0.f;
    }
}
__global__ void dec_init_kernel(const int* __restrict__ sos)
{
    int i = blockIdx.x * blockDim.x + threadIdx.x;
    if (i < BT * HDIM) {
        g_hs[0][0][i] = g_eL[0][i];
        g_hs[0][1][i] = g_eL[1][i];
        g_c[i] = 0.f;
    }
    if (i < BT) g_tok[i] = sos[0];
}

// ---------------- stage loader: 4 tiles (Ah, Al, Bh, Bl), k-block kb ---------
__device__ __forceinline__ void load_stage(
    uint32_t sb, int buf, int kb,
    const __half* __restrict__ Ah, const __half* __restrict__ Al,
    const __half* __restrict__ Bh, const __half* __restrict__ Bl,
    int m0, int n0, int tid)
{
    const __half* srcs[4] = {Ah, Al, Bh, Bl};
    const uint32_t base = sb + buf * BUF_B;
    const int row = tid >> 1;
    const int c0 = (tid & 1) * 4;
#pragma unroll
    for (int tl = 0; tl < 4; tl++) {
        const int r0 = (tl < 2) ? m0 : n0;
        const __half* src = srcs[tl] + (size_t)(r0 + row) * HDIM + kb * 64 + c0 * 8;
        uint32_t dst = base + tl * TILE_B + row * TROW_B + c0 * 16;
#pragma unroll
        for (int c = 0; c < 4; c++)
            cpa16(dst + c * 16, src + c * 8);
    }
}

// ---------------- fused LSTM step: fp16-split mma.sync GEMM + pointwise -----
// C = Ah.Bh + Ah.Bl + Al.Bh ; all three products from one SMEM stage.
// CTA 128x128, 8 warps (2M x 4N), warp tile 64x32, k-stage 64, double buffer.
__global__ __launch_bounds__(256, 1)
void lstm_step_mma(const int* __restrict__ phon, const int* __restrict__ lens,
                   int mode, int t)
{
    extern __shared__ char smem[];
    const uint32_t sb = smem_u32(smem);
    float* Cst = (float*)(smem + SM_C_OFF);

    const int tid  = threadIdx.x;
    const int lane = tid & 31;
    const int wid  = tid >> 5;
    const int wm = wid & 1, wn = wid >> 1;
    const int m0 = blockIdx.x * MT;
    const int n0 = blockIdx.y * NT;
    const int j0 = n0 >> 2;
    const int inPar = t & 1, outPar = inPar ^ 1;

    const __half* Ah = g_hs[inPar][0];
    const __half* Al = g_hs[inPar][1];
    const __half* Bh = g_Ws[mode][0];
    const __half* Bl = g_Ws[mode][1];

    float acc[4][4][4];
#pragma unroll
    for (int i = 0; i < 4; i++)
#pragma unroll
        for (int j = 0; j < 4; j++)
#pragma unroll
            for (int q = 0; q < 4; q++) acc[i][j][q] = 0.f;

    const int aRow = wm * 64 + (lane & 15);
    const int aCol = (lane >> 4) * 8;
    const int bRow = wn * 32 + ((lane & 16) >> 1) + (lane & 7);
    const int bCol = ((lane >> 3) & 1) * 8;

    load_stage(sb, 0, 0, Ah, Al, Bh, Bl, m0, n0, tid);
    cpa_commit();

    for (int kb = 0; kb < 4; kb++) {
        const int buf = kb & 1;
        if (kb < 3) {
            load_stage(sb, buf ^ 1, kb + 1, Ah, Al, Bh, Bl, m0, n0, tid);
            cpa_commit();
            cpa_wait<1>();
        } else {
            cpa_wait<0>();
        }
        __syncthreads();

        const uint32_t bAh = sb + buf * BUF_B;
        const uint32_t bAl = bAh + TILE_B;
        const uint32_t bBh = bAh + 2 * TILE_B;
        const uint32_t bBl = bAh + 3 * TILE_B;
#pragma unroll
        for (int k16 = 0; k16 < 4; k16++) {
            const uint32_t aOff = (uint32_t)(k16 * 16 + aCol) * 2;
            const uint32_t bOff = (uint32_t)(k16 * 16 + bCol) * 2;
            uint32_t ah[4][4], al[4][4], bh[2][4], bl[2][4];
#pragma unroll
            for (int mt = 0; mt < 4; mt++) {
                ldsm4(ah[mt], bAh + (uint32_t)(aRow + mt * 16) * TROW_B + aOff);
                ldsm4(al[mt], bAl + (uint32_t)(aRow + mt * 16) * TROW_B + aOff);
            }
#pragma unroll
            for (int bg = 0; bg < 2; bg++) {
                ldsm4(bh[bg], bBh + (uint32_t)(bRow + bg * 16) * TROW_B + bOff);
                ldsm4(bl[bg], bBl + (uint32_t)(bRow + bg * 16) * TROW_B + bOff);
            }
#pragma unroll
            for (int mt = 0; mt < 4; mt++)
#pragma unroll
                for (int nt = 0; nt < 4; nt++) {
                    const int g = nt >> 1, s = (nt & 1) * 2;
                    mma16816(acc[mt][nt], ah[mt], bh[g][s], bh[g][s + 1]);
                    mma16816(acc[mt][nt], ah[mt], bl[g][s], bl[g][s + 1]);
                    mma16816(acc[mt][nt], al[mt], bh[g][s], bh[g][s + 1]);
                }
        }
        __syncthreads();
    }

    // ---- stage accumulators to smem C (gate-interleaved columns) ----
#pragma unroll
    for (int mt = 0; mt < 4; mt++) {
#pragma unroll
        for (int nt = 0; nt < 4; nt++) {
            int r0 = wm * 64 + mt * 16 + (lane >> 2);
            int c0 = wn * 32 + nt * 8 + (lane & 3) * 2;
            *(float2*)&Cst[r0 * C_STRIDE + c0]       = make_float2(acc[mt][nt][0], acc[mt][nt][1]);
            *(float2*)&Cst[(r0 + 8) * C_STRIDE + c0] = make_float2(acc[mt][nt][2], acc[mt][nt][3]);
        }
    }
    __syncthreads();

    // ---- pointwise LSTM epilogue ----
    const float* projT = g_projP[mode];
#pragma unroll
    for (int i = 0; i < 16; i++) {
        int f = tid + i * 256;
        int lm = f >> 5, jl = f & 31;
        int m = m0 + lm;
        int tok = mode ? g_tok[m] : phon[m * TPH + t];
        float4 gv4 = *(const float4*)&Cst[lm * C_STRIDE + jl * 4];
        float4 pv  = *(const float4*)&projT[(size_t)tok * GDIM + (n0 + jl * 4)];
        float xi = gv4.x + pv.x;
        float xf = gv4.y + pv.y;
        float xg = gv4.z + pv.z;
        float xo = gv4.w + pv.w;
        float iv = 1.f / (1.f + expf(-xi));
        float fv = 1.f / (1.f + expf(-xf));
        float gg = tanhf(xg);
        float ov = 1.f / (1.f + expf(-xo));
        size_t idx = (size_t)m * HDIM + j0 + jl;
        float cn = fv * g_c[idx] + iv * gg;
        g_c[idx] = cn;
        float hv = ov * tanhf(cn);
        __half hi = __float2half_rn(hv);
        __half lo = __float2half_rn(hv - __half2float(hi));
        g_hs[outPar][0][idx] = hi;
        g_hs[outPar][1][idx] = lo;
        if (mode) {
            g_hf[idx] = hv;
        } else if (t == lens[m] - 1) {
            g_eL[0][idx] = hi; g_eL[1][idx] = lo;
        }
    }
}

// ---------------- decoder fc + argmax: 16 rows/block (128 blocks) -----------
__global__ void __launch_bounds__(256)
dec_fc_kernel(const float* __restrict__ fcW,
              const float* __restrict__ fcb,
              float* __restrict__ out,
              int t)
{
    const float* h = g_hf;

    __shared__ float As[16][20];
    __shared__ float Bs[16][264];

    const int tid = threadIdx.x;
    const int tv = tid & 31;
    const int tm = tid >> 5;
    const int m0 = blockIdx.x * 16;

    float acc[2][8];
#pragma unroll
    for (int i = 0; i < 2; i++)
#pragma unroll
        for (int j = 0; j < 8; j++) acc[i][j] = 0.f;

    for (int k0 = 0; k0 < HDIM; k0 += 16) {
        if (tid < 64) {
            int r = tid >> 2, kq = tid & 3;
            float4 v = *(const float4*)(h + (size_t)(m0 + r) * HDIM + k0 + kq * 4);
            As[kq * 4 + 0][r] = v.x; As[kq * 4 + 1][r] = v.y;
            As[kq * 4 + 2][r] = v.z; As[kq * 4 + 3][r] = v.w;
        }
#pragma unroll
        for (int i = 0; i < 4; i++) {
            int f = tid + i * 256;
            int row = f >> 2, kq = f & 3;
            float4 v = *(const float4*)(fcW + (size_t)row * HDIM + k0 + kq * 4);
            Bs[kq * 4 + 0][row] = v.x; Bs[kq * 4 + 1][row] = v.y;
            Bs[kq * 4 + 2][row] = v.z; Bs[kq * 4 + 3][row] = v.w;
        }
        __syncthreads();
#pragma unroll
        for (int kk = 0; kk < 16; kk++) {
            float2 a  = *(const float2*)&As[kk][tm * 2];
            float4 b0 = *(const float4*)&Bs[kk][tv * 8];
            float4 b1 = *(const float4*)&Bs[kk][tv * 8 + 4];
            float bv[8] = {b0.x, b0.y, b0.z, b0.w, b1.x, b1.y, b1.z, b1.w};
#pragma unroll
            for (int vi = 0; vi < 8; vi++) {
                acc[0][vi] += a.x * bv[vi];
                acc[1][vi] += a.y * bv[vi];
            }
        }
        __syncthreads();
    }

    float bias[8];
#pragma unroll
    for (int vi = 0; vi < 8; vi++) bias[vi] = fcb[tv * 8 + vi];

#pragma unroll
    for (int mi = 0; mi < 2; mi++) {
        const int m = m0 + tm * 2 + mi;
        float s[8];
#pragma unroll
        for (int vi = 0; vi < 8; vi++) s[vi] = acc[mi][vi] + bias[vi];

        float* orow = out + (size_t)m * (TPH * VOC) + (size_t)t * VOC + tv * 8;
        *(float4*)(orow)     = make_float4(s[0], s[1], s[2], s[3]);
        *(float4*)(orow + 4) = make_float4(s[4], s[5], s[6], s[7]);

        float bv = s[0];
        int   bi = tv * 8;
#pragma unroll
        for (int vi = 1; vi < 8; vi++)
            if (s[vi] > bv) { bv = s[vi]; bi = tv * 8 + vi; }
#pragma unroll
        for (int off = 16; off > 0; off >>= 1) {
            float ov = __shfl_xor_sync(0xffffffffu, bv, off);
            int   oi = __shfl_xor_sync(0xffffffffu, bi, off);
            if (ov > bv || (ov == bv && oi < bi)) { bv = ov; bi = oi; }
        }
        if (tv == 0) g_tok[m] = bi;
    }
}

// ---------------- launch ----------------
extern "C" void kernel_launch(void* const* d_in, const int* in_sizes, int n_in,
                              void* d_out, int out_size)
{
    const int*   phon   = (const int*)  d_in[0];
    const int*   plen   = (const int*)  d_in[1];
    const float* emb    = (const float*)d_in[2];
    const float* encWih = (const float*)d_in[3];
    const float* encWhh = (const float*)d_in[4];
    const float* encBih = (const float*)d_in[5];
    const float* encBhh = (const float*)d_in[6];
    const float* decWih = (const float*)d_in[7];
    const float* decWhh = (const float*)d_in[8];
    const float* decBih = (const float*)d_in[9];
    const float* decBhh = (const float*)d_in[10];
    const float* fcW    = (const float*)d_in[11];
    const float* fcb    = (const float*)d_in[12];
    const int*   sos    = (const int*)  d_in[13];
    float* out = (float*)d_out;

    cudaFuncSetAttribute(lstm_step_mma,
                         cudaFuncAttributeMaxDynamicSharedMemorySize, SM_TOTAL);

    split_w_kernel<<<(GDIM * HDIM + 255) / 256, 256>>>(encWhh, 0);
    split_w_kernel<<<(GDIM * HDIM + 255) / 256, 256>>>(decWhh, 1);
    dim3 pgrid(VOC, 4);
    proj_kernel<<<pgrid, 256>>>(emb, encWih, encBih, encBhh, 0);
    proj_kernel<<<pgrid, 256>>>(emb, decWih, decBih, decBhh, 1);

    init_kernel<<<(BT * HDIM + 255) / 256, 256>>>();

    dim3 grid(GRID_M, GRID_N);
    for (int t = 0; t < TPH; t++)
        lstm_step_mma<<<grid, 256, SM_TOTAL>>>(phon, plen, 0, t);

    dec_init_kernel<<<(BT * HDIM + 255) / 256, 256>>>(sos);

    for (int t = 0; t < TPH; t++) {
        lstm_step_mma<<<grid, 256, SM_TOTAL>>>(phon, plen, 1, t);
        dec_fc_kernel<<<BT / 16, 256>>>(fcW, fcb, out, t);
    }
}

// round 6
// speedup vs baseline: 1.4217x; 1.1848x over previous
#include <cuda_runtime.h>
#include <cuda_fp16.h>
#include <math.h>
#include <stdint.h>

#define BT   2048
#define TPH  32
#define EDIM 128
#define HDIM 256
#define GDIM 1024
#define VOC  256

#define MT 128
#define NT 128
#define GRID_M (BT / MT)     // 16
#define GRID_N (GDIM / NT)   // 8

// tiles: 128 rows x 64 k halfs, padded row stride 72 halfs (144 B)
#define TROW_B   144
#define TILE_B   (128 * TROW_B)          // 18432
#define BUF_B    (4 * TILE_B)            // Ah, Al, Bh, Bl = 73728
#define SM_C_OFF (2 * BUF_B)             // 147456
#define C_STRIDE 132
#define SM_TOTAL (SM_C_OFF + 128 * C_STRIDE * 4)   // 215040

// ---------------- device scratch ----------------
__device__ float   g_projP[2][VOC * GDIM];   // permuted proj tables (enc/dec)
__device__ __half  g_Ws[2][2][GDIM * HDIM];  // Whh fp16 splits (hi,lo), gate-interleaved rows
__device__ __half  g_hs[2][2][BT * HDIM];    // h fp16 splits, double buffered by parity
__device__ __half  g_eL[2][BT * HDIM];       // encoder-last h splits
__device__ float   g_c[BT * HDIM];
__device__ float   g_hf[BT * HDIM];          // fp32 h (decoder, for fc)
__device__ int     g_tok[BT];

// ---------------- fast pointwise (exp-based, ~1e-6 rel err) ----------------
__device__ __forceinline__ float fast_sigmoid(float x) {
    return __fdividef(1.f, 1.f + __expf(-x));
}
__device__ __forceinline__ float fast_tanh(float x) {
    return 1.f - __fdividef(2.f, __expf(2.f * x) + 1.f);
}

// ---------------- PTX helpers (portable: sm_80+) ----------------
__device__ __forceinline__ uint32_t smem_u32(const void* p) {
    uint32_t a;
    asm("{ .reg .u64 t; cvta.to.shared.u64 t, %1; cvt.u32.u64 %0, t; }" : "=r"(a) : "l"(p));
    return a;
}
__device__ __forceinline__ void cpa16(uint32_t saddr, const void* g) {
    asm volatile("cp.async.cg.shared.global [%0], [%1], 16;" :: "r"(saddr), "l"(g));
}
__device__ __forceinline__ void cpa_commit() {
    asm volatile("cp.async.commit_group;" ::: "memory");
}
template <int N>
__device__ __forceinline__ void cpa_wait() {
    asm volatile("cp.async.wait_group %0;" :: "n"(N) : "memory");
}
__device__ __forceinline__ void ldsm4(uint32_t* r, uint32_t addr) {
    asm volatile("ldmatrix.sync.aligned.m8n8.x4.shared.b16 {%0,%1,%2,%3}, [%4];"
        : "=r"(r[0]), "=r"(r[1]), "=r"(r[2]), "=r"(r[3]) : "r"(addr));
}
__device__ __forceinline__ void mma16816(float* c, const uint32_t* a,
                                         uint32_t b0, uint32_t b1) {
    asm volatile("mma.sync.aligned.m16n8k16.row.col.f32.f16.f16.f32 "
        "{%0,%1,%2,%3}, {%4,%5,%6,%7}, {%8,%9}, {%0,%1,%2,%3};"
        : "+f"(c[0]), "+f"(c[1]), "+f"(c[2]), "+f"(c[3])
        : "r"(a[0]), "r"(a[1]), "r"(a[2]), "r"(a[3]), "r"(b0), "r"(b1));
}

// ---------------- prep #1: split BOTH Whh into 2 fp16 planes, gate-interleaved
__global__ void split_w_kernel(const float* __restrict__ Wenc,
                               const float* __restrict__ Wdec)
{
    int gidx = blockIdx.x * blockDim.x + threadIdx.x;   // over 2*GDIM*HDIM
    if (gidx >= 2 * GDIM * HDIM) return;
    int which = gidx >= GDIM * HDIM;
    int idx = gidx - which * (GDIM * HDIM);
    const float* W = which ? Wdec : Wenc;
    int np = idx >> 8, k = idx & 255;
    int j = np >> 2, g = np & 3;                        // n' = j*4 + g
    float w = W[(size_t)(g * HDIM + j) * HDIM + k];
    __half hi = __float2half_rn(w);
    __half lo = __float2half_rn(w - __half2float(hi));
    g_Ws[which][0][idx] = hi;
    g_Ws[which][1][idx] = lo;
}

// ---------------- prep #2: permuted proj tables (both enc & dec) ------------
__global__ void proj_kernel(const float* __restrict__ emb,
                            const float* __restrict__ Wenc,
                            const float* __restrict__ b1e,
                            const float* __restrict__ b2e,
                            const float* __restrict__ Wdec,
                            const float* __restrict__ b1d,
                            const float* __restrict__ b2d)
{
    int which = blockIdx.z;
    const float* W  = which ? Wdec : Wenc;
    const float* b1 = which ? b1d : b1e;
    const float* b2 = which ? b2d : b2e;
    int v = blockIdx.x;
    __shared__ float es[EDIM];
    int tid = threadIdx.x;
    if (tid < EDIM) es[tid] = emb[v * EDIM + tid];
    __syncthreads();
    int n = blockIdx.y * 256 + tid;
    const float4* wr = (const float4*)(W + (size_t)n * EDIM);
    float acc = 0.f;
#pragma unroll
    for (int k4 = 0; k4 < EDIM / 4; k4++) {
        float4 w = wr[k4];
        acc += es[k4 * 4 + 0] * w.x + es[k4 * 4 + 1] * w.y
             + es[k4 * 4 + 2] * w.z + es[k4 * 4 + 3] * w.w;
    }
    int np = (n & 255) * 4 + (n >> 8);
    g_projP[which][(size_t)v * GDIM + np] = acc + b1[n] + b2[n];
}

// ---------------- init / dec-init ----------------
__global__ void init_kernel()
{
    int i = blockIdx.x * blockDim.x + threadIdx.x;
    if (i < BT * HDIM) {
        __half z = __float2half_rn(0.f);
        g_hs[0][0][i] = z; g_hs[0][1][i] = z;
        g_c[i] = 0.f;
    }
}
__global__ void dec_init_kernel(const int* __restrict__ sos)
{
    int i = blockIdx.x * blockDim.x + threadIdx.x;
    if (i < BT * HDIM) {
        g_hs[0][0][i] = g_eL[0][i];
        g_hs[0][1][i] = g_eL[1][i];
        g_c[i] = 0.f;
    }
    if (i < BT) g_tok[i] = sos[0];
}

// ---------------- stage loader: 4 tiles (Ah, Al, Bh, Bl), k-block kb ---------
__device__ __forceinline__ void load_stage(
    uint32_t sb, int buf, int kb,
    const __half* __restrict__ Ah, const __half* __restrict__ Al,
    const __half* __restrict__ Bh, const __half* __restrict__ Bl,
    int m0, int n0, int tid)
{
    const __half* srcs[4] = {Ah, Al, Bh, Bl};
    const uint32_t base = sb + buf * BUF_B;
    const int row = tid >> 1;
    const int c0 = (tid & 1) * 4;
#pragma unroll
    for (int tl = 0; tl < 4; tl++) {
        const int r0 = (tl < 2) ? m0 : n0;
        const __half* src = srcs[tl] + (size_t)(r0 + row) * HDIM + kb * 64 + c0 * 8;
        uint32_t dst = base + tl * TILE_B + row * TROW_B + c0 * 16;
#pragma unroll
        for (int c = 0; c < 4; c++)
            cpa16(dst + c * 16, src + c * 8);
    }
}

// ---------------- fused LSTM step: fp16-split mma.sync GEMM + pointwise -----
// C = Ah.Bh + Ah.Bl + Al.Bh ; 3 passes of 16 independent MMAs each.
__global__ __launch_bounds__(256, 1)
void lstm_step_mma(const int* __restrict__ phon, const int* __restrict__ lens,
                   int mode, int t)
{
    extern __shared__ char smem[];
    const uint32_t sb = smem_u32(smem);
    float* Cst = (float*)(smem + SM_C_OFF);

    const int tid  = threadIdx.x;
    const int lane = tid & 31;
    const int wid  = tid >> 5;
    const int wm = wid & 1, wn = wid >> 1;
    const int m0 = blockIdx.x * MT;
    const int n0 = blockIdx.y * NT;
    const int j0 = n0 >> 2;
    const int inPar = t & 1, outPar = inPar ^ 1;

    const __half* Ah = g_hs[inPar][0];
    const __half* Al = g_hs[inPar][1];
    const __half* Bh = g_Ws[mode][0];
    const __half* Bl = g_Ws[mode][1];

    float acc[4][4][4];
#pragma unroll
    for (int i = 0; i < 4; i++)
#pragma unroll
        for (int j = 0; j < 4; j++)
#pragma unroll
            for (int q = 0; q < 4; q++) acc[i][j][q] = 0.f;

    const int aRow = wm * 64 + (lane & 15);
    const int aCol = (lane >> 4) * 8;
    const int bRow = wn * 32 + ((lane & 16) >> 1) + (lane & 7);
    const int bCol = ((lane >> 3) & 1) * 8;

    load_stage(sb, 0, 0, Ah, Al, Bh, Bl, m0, n0, tid);
    cpa_commit();

    for (int kb = 0; kb < 4; kb++) {
        const int buf = kb & 1;
        if (kb < 3) {
            load_stage(sb, buf ^ 1, kb + 1, Ah, Al, Bh, Bl, m0, n0, tid);
            cpa_commit();
            cpa_wait<1>();
        } else {
            cpa_wait<0>();
        }
        __syncthreads();

        const uint32_t bAh = sb + buf * BUF_B;
        const uint32_t bAl = bAh + TILE_B;
        const uint32_t bBh = bAh + 2 * TILE_B;
        const uint32_t bBl = bAh + 3 * TILE_B;
#pragma unroll
        for (int k16 = 0; k16 < 4; k16++) {
            const uint32_t aOff = (uint32_t)(k16 * 16 + aCol) * 2;
            const uint32_t bOff = (uint32_t)(k16 * 16 + bCol) * 2;
            uint32_t ah[4][4], al[4][4], bh[2][4], bl[2][4];
#pragma unroll
            for (int mt = 0; mt < 4; mt++) {
                ldsm4(ah[mt], bAh + (uint32_t)(aRow + mt * 16) * TROW_B + aOff);
                ldsm4(al[mt], bAl + (uint32_t)(aRow + mt * 16) * TROW_B + aOff);
            }
#pragma unroll
            for (int bg = 0; bg < 2; bg++) {
                ldsm4(bh[bg], bBh + (uint32_t)(bRow + bg * 16) * TROW_B + bOff);
                ldsm4(bl[bg], bBl + (uint32_t)(bRow + bg * 16) * TROW_B + bOff);
            }
            // pass 1: Ah*Bh (16 independent MMAs)
#pragma unroll
            for (int mt = 0; mt < 4; mt++)
#pragma unroll
                for (int nt = 0; nt < 4; nt++) {
                    const int g = nt >> 1, s = (nt & 1) * 2;
                    mma16816(acc[mt][nt], ah[mt], bh[g][s], bh[g][s + 1]);
                }
            // pass 2: Ah*Bl
#pragma unroll
            for (int mt = 0; mt < 4; mt++)
#pragma unroll
                for (int nt = 0; nt < 4; nt++) {
                    const int g = nt >> 1, s = (nt & 1) * 2;
                    mma16816(acc[mt][nt], ah[mt], bl[g][s], bl[g][s + 1]);
                }
            // pass 3: Al*Bh
#pragma unroll
            for (int mt = 0; mt < 4; mt++)
#pragma unroll
                for (int nt = 0; nt < 4; nt++) {
                    const int g = nt >> 1, s = (nt & 1) * 2;
                    mma16816(acc[mt][nt], al[mt], bh[g][s], bh[g][s + 1]);
                }
        }
        __syncthreads();
    }

    // ---- stage accumulators to smem C (gate-interleaved columns) ----
#pragma unroll
    for (int mt = 0; mt < 4; mt++) {
#pragma unroll
        for (int nt = 0; nt < 4; nt++) {
            int r0 = wm * 64 + mt * 16 + (lane >> 2);
            int c0 = wn * 32 + nt * 8 + (lane & 3) * 2;
            *(float2*)&Cst[r0 * C_STRIDE + c0]       = make_float2(acc[mt][nt][0], acc[mt][nt][1]);
            *(float2*)&Cst[(r0 + 8) * C_STRIDE + c0] = make_float2(acc[mt][nt][2], acc[mt][nt][3]);
        }
    }
    __syncthreads();

    // ---- pointwise LSTM epilogue (fast exp-based activations) ----
    const float* projT = g_projP[mode];
#pragma unroll
    for (int i = 0; i < 16; i++) {
        int f = tid + i * 256;
        int lm = f >> 5, jl = f & 31;
        int m = m0 + lm;
        int tok = mode ? g_tok[m] : phon[m * TPH + t];
        float4 gv4 = *(const float4*)&Cst[lm * C_STRIDE + jl * 4];
        float4 pv  = *(const float4*)&projT[(size_t)tok * GDIM + (n0 + jl * 4)];
        float xi = gv4.x + pv.x;
        float xf = gv4.y + pv.y;
        float xg = gv4.z + pv.z;
        float xo = gv4.w + pv.w;
        float iv = fast_sigmoid(xi);
        float fv = fast_sigmoid(xf);
        float gg = fast_tanh(xg);
        float ov = fast_sigmoid(xo);
        size_t idx = (size_t)m * HDIM + j0 + jl;
        float cn = fv * g_c[idx] + iv * gg;
        g_c[idx] = cn;
        float hv = ov * fast_tanh(cn);
        __half hi = __float2half_rn(hv);
        __half lo = __float2half_rn(hv - __half2float(hi));
        g_hs[outPar][0][idx] = hi;
        g_hs[outPar][1][idx] = lo;
        if (mode) {
            g_hf[idx] = hv;
        } else if (t == lens[m] - 1) {
            g_eL[0][idx] = hi; g_eL[1][idx] = lo;
        }
    }
}

// ---------------- decoder fc + argmax: 16 rows/block (128 blocks) -----------
__global__ void __launch_bounds__(256)
dec_fc_kernel(const float* __restrict__ fcW,
              const float* __restrict__ fcb,
              float* __restrict__ out,
              int t)
{
    const float* h = g_hf;

    __shared__ float As[16][20];
    __shared__ float Bs[16][264];

    const int tid = threadIdx.x;
    const int tv = tid & 31;
    const int tm = tid >> 5;
    const int m0 = blockIdx.x * 16;

    float acc[2][8];
#pragma unroll
    for (int i = 0; i < 2; i++)
#pragma unroll
        for (int j = 0; j < 8; j++) acc[i][j] = 0.f;

    for (int k0 = 0; k0 < HDIM; k0 += 16) {
        if (tid < 64) {
            int r = tid >> 2, kq = tid & 3;
            float4 v = *(const float4*)(h + (size_t)(m0 + r) * HDIM + k0 + kq * 4);
            As[kq * 4 + 0][r] = v.x; As[kq * 4 + 1][r] = v.y;
            As[kq * 4 + 2][r] = v.z; As[kq * 4 + 3][r] = v.w;
        }
#pragma unroll
        for (int i = 0; i < 4; i++) {
            int f = tid + i * 256;
            int row = f >> 2, kq = f & 3;
            float4 v = *(const float4*)(fcW + (size_t)row * HDIM + k0 + kq * 4);
            Bs[kq * 4 + 0][row] = v.x; Bs[kq * 4 + 1][row] = v.y;
            Bs[kq * 4 + 2][row] = v.z; Bs[kq * 4 + 3][row] = v.w;
        }
        __syncthreads();
#pragma unroll
        for (int kk = 0; kk < 16; kk++) {
            float2 a  = *(const float2*)&As[kk][tm * 2];
            float4 b0 = *(const float4*)&Bs[kk][tv * 8];
            float4 b1 = *(const float4*)&Bs[kk][tv * 8 + 4];
            float bv[8] = {b0.x, b0.y, b0.z, b0.w, b1.x, b1.y, b1.z, b1.w};
#pragma unroll
            for (int vi = 0; vi < 8; vi++) {
                acc[0][vi] += a.x * bv[vi];
                acc[1][vi] += a.y * bv[vi];
            }
        }
        __syncthreads();
    }

    float bias[8];
#pragma unroll
    for (int vi = 0; vi < 8; vi++) bias[vi] = fcb[tv * 8 + vi];

#pragma unroll
    for (int mi = 0; mi < 2; mi++) {
        const int m = m0 + tm * 2 + mi;
        float s[8];
#pragma unroll
        for (int vi = 0; vi < 8; vi++) s[vi] = acc[mi][vi] + bias[vi];

        float* orow = out + (size_t)m * (TPH * VOC) + (size_t)t * VOC + tv * 8;
        *(float4*)(orow)     = make_float4(s[0], s[1], s[2], s[3]);
        *(float4*)(orow + 4) = make_float4(s[4], s[5], s[6], s[7]);

        float bv = s[0];
        int   bi = tv * 8;
#pragma unroll
        for (int vi = 1; vi < 8; vi++)
            if (s[vi] > bv) { bv = s[vi]; bi = tv * 8 + vi; }
#pragma unroll
        for (int off = 16; off > 0; off >>= 1) {
            float ov = __shfl_xor_sync(0xffffffffu, bv, off);
            int   oi = __shfl_xor_sync(0xffffffffu, bi, off);
            if (ov > bv || (ov == bv && oi < bi)) { bv = ov; bi = oi; }
        }
        if (tv == 0) g_tok[m] = bi;
    }
}

// ---------------- launch ----------------
extern "C" void kernel_launch(void* const* d_in, const int* in_sizes, int n_in,
                              void* d_out, int out_size)
{
    const int*   phon   = (const int*)  d_in[0];
    const int*   plen   = (const int*)  d_in[1];
    const float* emb    = (const float*)d_in[2];
    const float* encWih = (const float*)d_in[3];
    const float* encWhh = (const float*)d_in[4];
    const float* encBih = (const float*)d_in[5];
    const float* encBhh = (const float*)d_in[6];
    const float* decWih = (const float*)d_in[7];
    const float* decWhh = (const float*)d_in[8];
    const float* decBih = (const float*)d_in[9];
    const float* decBhh = (const float*)d_in[10];
    const float* fcW    = (const float*)d_in[11];
    const float* fcb    = (const float*)d_in[12];
    const int*   sos    = (const int*)  d_in[13];
    float* out = (float*)d_out;

    cudaFuncSetAttribute(lstm_step_mma,
                         cudaFuncAttributeMaxDynamicSharedMemorySize, SM_TOTAL);

    // launch #1..#3: prep (merged so lstm_step_mma lands in the ncu window)
    split_w_kernel<<<(2 * GDIM * HDIM + 255) / 256, 256>>>(encWhh, decWhh);
    dim3 pgrid(VOC, 4, 2);
    proj_kernel<<<pgrid, 256>>>(emb, encWih, encBih, encBhh, decWih, decBih, decBhh);
    init_kernel<<<(BT * HDIM + 255) / 256, 256>>>();

    dim3 grid(GRID_M, GRID_N);
    for (int t = 0; t < TPH; t++)
        lstm_step_mma<<<grid, 256, SM_TOTAL>>>(phon, plen, 0, t);

    dec_init_kernel<<<(BT * HDIM + 255) / 256, 256>>>(sos);

    for (int t = 0; t < TPH; t++) {
        lstm_step_mma<<<grid, 256, SM_TOTAL>>>(phon, plen, 1, t);
        dec_fc_kernel<<<BT / 16, 256>>>(fcW, fcb, out, t);
    }
}